// round 15
// baseline (speedup 1.0000x reference)
#include <cuda_runtime.h>
#include <cstdint>

// Problem constants (fixed by the reference)
#define B_ 16
#define H_ 100
#define W_ 100
#define C_ 256
#define R_ 128
#define P_ 7
#define CELLS (P_ * P_)   // 49

__device__ __forceinline__ float4 lerp4(float4 a, float4 b, float4 c, float4 d,
                                        float fx, float fy)
{
    float4 o;
    float top, bot;
    top = a.x + (b.x - a.x) * fx;  bot = c.x + (d.x - c.x) * fx;  o.x = top + (bot - top) * fy;
    top = a.y + (b.y - a.y) * fx;  bot = c.y + (d.y - c.y) * fx;  o.y = top + (bot - top) * fy;
    top = a.z + (b.z - a.z) * fx;  bot = c.z + (d.z - c.z) * fx;  o.z = top + (bot - top) * fy;
    top = a.w + (b.w - a.w) * fx;  bot = c.w + (d.w - c.w) * fx;  o.w = top + (bot - top) * fy;
    return o;
}

__device__ __forceinline__ void pref_l1(const void* p)
{
    asm volatile("prefetch.global.L1 [%0];" :: "l"(p));
}

// TWO CTAs per ROI (channel halves), grid = 4096, 224 threads = 7 warps.
// Warp w = pooling row py=w, sweeping px=0..6 (row mapping keeps a warp's
// corner loads on two feature rows -> L1 reuse; R12 structure, best so far).
// NEW: each iteration issues prefetch.global.L1 for the NEXT cell's 4 corners.
// Prefetch has no register target and no scoreboard, so it adds outstanding
// memory parallelism at ZERO occupancy cost — the lever every register-based
// MLP attempt (R4/R5/R10/R13) couldn't reach. The real LDGs one iteration
// later hit L1 (~39cyc) instead of L2/DRAM (250-580cyc).
__global__ __launch_bounds__(224, 8) void roi_pool_kernel(
    const float* __restrict__ fm,   // [B, H, W, C]
    const int*   __restrict__ rois, // [B, R, 4]  (x, y, h, w)
    float*       __restrict__ out)  // [B, R, P, P, C]
{
    __shared__ int4   s_off[CELLS];   // float4-unit offsets of the 4 corners
    __shared__ float2 s_fr[CELLS];    // (fx, fy)

    const int roi_idx = blockIdx.x >> 1;        // b*R + r
    const int chalf   = blockIdx.x & 1;         // channel half 0/1
    const int b = roi_idx >> 7;                 // R_ = 128
    const int tid = threadIdx.x;

    if (tid < CELLS) {
        const int4 roi = __ldg((const int4*)(rois + (size_t)roi_idx * 4));
        const int x = roi.x, y = roi.y, h = roi.z, w = roi.w;

        const int py = tid / P_;
        const int px = tid - py * P_;

        // y axis: src = (py+0.5)/P * h - 0.5, clipped to [0, h-1]
        const float hf = (float)h;
        float sy = ((float)py + 0.5f) * (1.0f / P_) * hf - 0.5f;
        sy = fminf(fmaxf(sy, 0.0f), hf - 1.0f);
        int   y0 = (int)floorf(sy);
        const float fy = sy - (float)y0;
        y0 += y;
        const int y1 = min(y0 + 1, y + h - 1);

        // x axis
        const float wf = (float)w;
        float sx = ((float)px + 0.5f) * (1.0f / P_) * wf - 0.5f;
        sx = fminf(fmaxf(sx, 0.0f), wf - 1.0f);
        int   x0 = (int)floorf(sx);
        const float fx = sx - (float)x0;
        x0 += x;
        const int x1 = min(x0 + 1, x + w - 1);

        // offsets in float4 units (C_/4 = 64 per pixel row)
        s_off[tid] = make_int4((y0 * W_ + x0) * (C_ / 4),
                               (y0 * W_ + x1) * (C_ / 4),
                               (y1 * W_ + x0) * (C_ / 4),
                               (y1 * W_ + x1) * (C_ / 4));
        s_fr[tid] = make_float2(fx, fy);
    }
    __syncthreads();

    const int wrp = tid >> 5;       // warp = pooling row py (0..6)
    const int ct  = tid & 31;       // channel thread (float4 group within half)

    const float4* base  = (const float4*)(fm + (size_t)b * (H_ * W_ * C_))
                          + (chalf << 5) + ct;
    float4*       obase = (float4*)(out + (size_t)roi_idx * (CELLS * C_))
                          + (chalf << 5) + ct;

    const int cell0 = wrp * P_;     // first cell of this row

    // Tuple for the first cell.
    int4   off = s_off[cell0];
    float2 fr  = s_fr[cell0];

    #pragma unroll
    for (int px = 0; px < P_; px++) {
        const int cell = cell0 + px;

        // Next cell's tuple + L1 prefetch of its 4 corners. Prefetches go out
        // ~400 cycles before the corresponding LDGs execute.
        int4   noff;
        float2 nfr;
        if (px < P_ - 1) {
            noff = s_off[cell + 1];
            nfr  = s_fr[cell + 1];
            pref_l1(base + noff.x);
            pref_l1(base + noff.y);
            pref_l1(base + noff.z);
            pref_l1(base + noff.w);
        }

        const float4 a = __ldg(base + off.x);
        const float4 bq = __ldg(base + off.y);
        const float4 c = __ldg(base + off.z);
        const float4 d = __ldg(base + off.w);

        __stcs(obase + cell * (C_ / 4), lerp4(a, bq, c, d, fr.x, fr.y));

        if (px < P_ - 1) { off = noff; fr = nfr; }
    }
}

extern "C" void kernel_launch(void* const* d_in, const int* in_sizes, int n_in,
                              void* d_out, int out_size)
{
    const float* fm   = (const float*)d_in[0];
    const int*   rois = (const int*)d_in[1];
    float*       out  = (float*)d_out;

    roi_pool_kernel<<<B_ * R_ * 2, 224>>>(fm, rois, out);
}

// round 16
// speedup vs baseline: 1.1043x; 1.1043x over previous
#include <cuda_runtime.h>
#include <cstdint>

// Problem constants (fixed by the reference)
#define B_ 16
#define H_ 100
#define W_ 100
#define C_ 256
#define R_ 128
#define P_ 7
#define CELLS (P_ * P_)   // 49

__device__ __forceinline__ float4 lerp4(float4 a, float4 b, float4 c, float4 d,
                                        float fx, float fy)
{
    float4 o;
    float top, bot;
    top = a.x + (b.x - a.x) * fx;  bot = c.x + (d.x - c.x) * fx;  o.x = top + (bot - top) * fy;
    top = a.y + (b.y - a.y) * fx;  bot = c.y + (d.y - c.y) * fx;  o.y = top + (bot - top) * fy;
    top = a.z + (b.z - a.z) * fx;  bot = c.z + (d.z - c.z) * fx;  o.z = top + (bot - top) * fy;
    top = a.w + (b.w - a.w) * fx;  bot = c.w + (d.w - c.w) * fx;  o.w = top + (bot - top) * fy;
    return o;
}

// TWO CTAs per ROI (channel halves), grid = 4096, 224 threads = 7 warps.
// Warp w = pooling row py=w (keeps a warp's 28 corner loads on two feature
// rows -> L1 reuse). This is the R12 structure — the measured optimum of the
// design space (L1tex crossbar is the binding resource at ~63%; every
// register-based or register-free MLP scheme measured worse).
// NEW vs R12: each warp sweeps its row starting at a skewed px offset
// ((warp + block) mod 7), decorrelating the moment all ~63 resident warps/SM
// front-batch their 4 LDGs into the L1tex queue (cross-CTA queue-contention
// spread term). Zero extra registers, zero extra bytes, identical reuse set.
__global__ __launch_bounds__(224, 9) void roi_pool_kernel(
    const float* __restrict__ fm,   // [B, H, W, C]
    const int*   __restrict__ rois, // [B, R, 4]  (x, y, h, w)
    float*       __restrict__ out)  // [B, R, P, P, C]
{
    __shared__ int4   s_off[CELLS];   // float4-unit offsets of the 4 corners
    __shared__ float2 s_fr[CELLS];    // (fx, fy)

    const int roi_idx = blockIdx.x >> 1;        // b*R + r
    const int chalf   = blockIdx.x & 1;         // channel half 0/1
    const int b = roi_idx >> 7;                 // R_ = 128
    const int tid = threadIdx.x;

    if (tid < CELLS) {
        const int4 roi = __ldg((const int4*)(rois + (size_t)roi_idx * 4));
        const int x = roi.x, y = roi.y, h = roi.z, w = roi.w;

        const int py = tid / P_;
        const int px = tid - py * P_;

        // y axis: src = (py+0.5)/P * h - 0.5, clipped to [0, h-1]
        const float hf = (float)h;
        float sy = ((float)py + 0.5f) * (1.0f / P_) * hf - 0.5f;
        sy = fminf(fmaxf(sy, 0.0f), hf - 1.0f);
        int   y0 = (int)floorf(sy);
        const float fy = sy - (float)y0;
        y0 += y;
        const int y1 = min(y0 + 1, y + h - 1);

        // x axis
        const float wf = (float)w;
        float sx = ((float)px + 0.5f) * (1.0f / P_) * wf - 0.5f;
        sx = fminf(fmaxf(sx, 0.0f), wf - 1.0f);
        int   x0 = (int)floorf(sx);
        const float fx = sx - (float)x0;
        x0 += x;
        const int x1 = min(x0 + 1, x + w - 1);

        // offsets in float4 units (C_/4 = 64 per pixel row)
        s_off[tid] = make_int4((y0 * W_ + x0) * (C_ / 4),
                               (y0 * W_ + x1) * (C_ / 4),
                               (y1 * W_ + x0) * (C_ / 4),
                               (y1 * W_ + x1) * (C_ / 4));
        s_fr[tid] = make_float2(fx, fy);
    }
    __syncthreads();

    const int wrp = tid >> 5;       // warp = pooling row py (0..6)
    const int ct  = tid & 31;       // channel thread (float4 group within half)

    const float4* base  = (const float4*)(fm + (size_t)b * (H_ * W_ * C_))
                          + (chalf << 5) + ct;
    float4*       obase = (float4*)(out + (size_t)roi_idx * (CELLS * C_))
                          + (chalf << 5) + ct;

    const int cell0 = wrp * P_;                    // first cell of this row
    const int skew  = (wrp + (int)blockIdx.x) % P_; // per-warp start offset

    // First (skewed) cell's tuple.
    int px  = skew;
    int4   off = s_off[cell0 + px];
    float2 fr  = s_fr[cell0 + px];

    #pragma unroll
    for (int j = 0; j < P_; j++) {
        const int cell = cell0 + px;

        // Next (rotated) cell's tuple, fetched before this cell's data so the
        // LDS sits off the LDG critical path.
        int    npx = px + 1;
        if (npx == P_) npx = 0;
        int4   noff;
        float2 nfr;
        if (j < P_ - 1) {
            noff = s_off[cell0 + npx];
            nfr  = s_fr[cell0 + npx];
        }

        const float4 a = __ldg(base + off.x);
        const float4 bq = __ldg(base + off.y);
        const float4 c = __ldg(base + off.z);
        const float4 d = __ldg(base + off.w);

        __stcs(obase + cell * (C_ / 4), lerp4(a, bq, c, d, fr.x, fr.y));

        if (j < P_ - 1) { px = npx; off = noff; fr = nfr; }
    }
}

extern "C" void kernel_launch(void* const* d_in, const int* in_sizes, int n_in,
                              void* d_out, int out_size)
{
    const float* fm   = (const float*)d_in[0];
    const int*   rois = (const int*)d_in[1];
    float*       out  = (float*)d_out;

    roi_pool_kernel<<<B_ * R_ * 2, 224>>>(fm, rois, out);
}

// round 17
// speedup vs baseline: 1.1061x; 1.0016x over previous
#include <cuda_runtime.h>
#include <cstdint>

// Problem constants (fixed by the reference)
#define B_ 16
#define H_ 100
#define W_ 100
#define C_ 256
#define R_ 128
#define P_ 7
#define CELLS (P_ * P_)   // 49

__device__ __forceinline__ float4 lerp4(float4 a, float4 b, float4 c, float4 d,
                                        float fx, float fy)
{
    float4 o;
    float top, bot;
    top = a.x + (b.x - a.x) * fx;  bot = c.x + (d.x - c.x) * fx;  o.x = top + (bot - top) * fy;
    top = a.y + (b.y - a.y) * fx;  bot = c.y + (d.y - c.y) * fx;  o.y = top + (bot - top) * fy;
    top = a.z + (b.z - a.z) * fx;  bot = c.z + (d.z - c.z) * fx;  o.z = top + (bot - top) * fy;
    top = a.w + (b.w - a.w) * fx;  bot = c.w + (d.w - c.w) * fx;  o.w = top + (bot - top) * fy;
    return o;
}

// Fully WARP-AUTONOMOUS kernel: no smem, no __syncthreads. One warp = one
// (roi, pooling-row, channel-half) unit. The y-tuple is warp-uniform; the
// per-px x-tuples are computed by lanes 0..6 and broadcast with __shfl_sync
// (26cyc, off the LDG critical path — replaces the smem table + barrier of
// R3-R16). Motivation: all barrier variants pinned achieved occupancy ~20%
// below theoretical (CTA-coupled start bursts + slowest-warp retirement);
// independent warps start memory work immediately and retire individually.
// 128 threads = 4 independent warps; launch_bounds(128,16) targets 32 regs ->
// 64 warps/SM theoretical. Row mapping keeps each warp's 28 corner loads on
// two feature rows for L1 reuse.
__global__ __launch_bounds__(128, 16) void roi_pool_kernel(
    const float* __restrict__ fm,   // [B, H, W, C]
    const int*   __restrict__ rois, // [B, R, 4]  (x, y, h, w)
    float*       __restrict__ out)  // [B, R, P, P, C]
{
    // Global warp id -> (roi, row, chalf)
    const int tid = threadIdx.x;
    const int wg  = blockIdx.x * 4 + (tid >> 5);   // 0 .. 28671
    const int ct  = tid & 31;                      // channel thread

    const int roi_idx = wg / 14;                   // b*R + r
    const int rem     = wg - roi_idx * 14;
    const int chalf   = (rem >= P_) ? 1 : 0;
    const int row     = rem - chalf * P_;          // pooling row py (0..6)
    const int b       = roi_idx >> 7;              // R_ = 128

    const int4 roi = __ldg((const int4*)(rois + (size_t)roi_idx * 4));
    const int x = roi.x, y = roi.y, h = roi.z, w = roi.w;

    // y axis (warp-uniform): src = (row+0.5)/P * h - 0.5, clipped to [0, h-1]
    const float hf = (float)h;
    float sy = ((float)row + 0.5f) * (1.0f / P_) * hf - 0.5f;
    sy = fminf(fmaxf(sy, 0.0f), hf - 1.0f);
    int   y0 = (int)floorf(sy);
    const float fy = sy - (float)y0;
    y0 += y;
    const int y1 = min(y0 + 1, y + h - 1);

    // x axis: lane l (l<7) computes the tuple for px=l; broadcast later.
    const int pxm = (ct < P_) ? ct : 0;
    const float wf = (float)w;
    float sx = ((float)pxm + 0.5f) * (1.0f / P_) * wf - 0.5f;
    sx = fminf(fmaxf(sx, 0.0f), wf - 1.0f);
    int   x0m = (int)floorf(sx);
    const float fxm = sx - (float)x0m;
    x0m += x;
    const int x1m = min(x0m + 1, x + w - 1);

    // Row bases in float4 units (C_/4 = 64 per pixel)
    const int rb0 = y0 * W_;
    const int rb1 = y1 * W_;

    const float4* base  = (const float4*)(fm + (size_t)b * (H_ * W_ * C_))
                          + (chalf << 5) + ct;
    float4*       obase = (float4*)(out + (size_t)roi_idx * (CELLS * C_))
                          + (chalf << 5) + ct + (row * P_) * (C_ / 4);

    #pragma unroll
    for (int px = 0; px < P_; px++) {
        const int   xx0 = __shfl_sync(0xffffffffu, x0m, px);
        const int   xx1 = __shfl_sync(0xffffffffu, x1m, px);
        const float fx  = __shfl_sync(0xffffffffu, fxm, px);

        const float4 a = __ldg(base + (rb0 + xx0) * (C_ / 4));
        const float4 bq = __ldg(base + (rb0 + xx1) * (C_ / 4));
        const float4 c = __ldg(base + (rb1 + xx0) * (C_ / 4));
        const float4 d = __ldg(base + (rb1 + xx1) * (C_ / 4));

        __stcs(obase + px * (C_ / 4), lerp4(a, bq, c, d, fx, fy));
    }
}

extern "C" void kernel_launch(void* const* d_in, const int* in_sizes, int n_in,
                              void* d_out, int out_size)
{
    const float* fm   = (const float*)d_in[0];
    const int*   rois = (const int*)d_in[1];
    float*       out  = (float*)d_out;

    // 2048 ROIs x 7 rows x 2 channel halves = 28672 warps; 4 warps per CTA.
    roi_pool_kernel<<<(B_ * R_ * P_ * 2) / 4, 128>>>(fm, rois, out);
}